// round 1
// baseline (speedup 1.0000x reference)
#include <cuda_runtime.h>

// Problem constants (UP=3, DOWN=2, Lh=63, Lb=51)
#define R_OUT 8                    // same-phase outputs per thread
#define BLOCK_T 384                // 3 phase groups x 128 threads
#define OUT_PER_BLOCK 3072         // 3 * 128 * R_OUT
#define TILE_X 2104                // 256*R_OUT + 56
#define OS_SIZE 3168               // 3072 + 96 (bank-conflict padding)

// Combined filter C[r] = sum_s b[s]*h[r-2s], r in [0,163). Stored as per-phase
// reversed tap-pairs: cpairs[p*28+s] = (Cp[55-2s], Cp[54-2s]) with Cp[i]=C[p+3i] (0-padded).
__device__ float2 g_cpairs[84];

__global__ void prep_kernel(const float* __restrict__ h, const float* __restrict__ b) {
    __shared__ float C[163];
    int tid = threadIdx.x;
    if (tid < 163) {
        float acc = 0.0f;
        #pragma unroll
        for (int s = 0; s < 51; s++) {
            int idx = tid - 2 * s;
            if (idx >= 0 && idx < 63) acc = fmaf(b[s], h[idx], acc);
        }
        C[tid] = acc;
    }
    __syncthreads();
    if (tid < 84) {
        int p = tid / 28, s = tid % 28;
        int rh = p + 165 - 6 * s;  // C index for tap i_hi = 55-2s
        int rl = p + 162 - 6 * s;  // C index for tap i_lo = 54-2s
        float2 v;
        v.x = (rh <= 162) ? C[rh] : 0.0f;
        v.y = (rl <= 162) ? C[rl] : 0.0f;
        g_cpairs[tid] = v;
    }
}

// Main fused kernel: out[j] = sum_m x[m]*C[2j+32-3m] for j in [0, n_out).
// Phase p = (2j+2)%3; M(j) = (2j+32-p)/3; out[j] = sum_i x[M-i]*C[p+3i].
// Thread layout: group g = tid/128 handles j == g (mod 3), p = 2-g.
// Each thread: R_OUT outputs j0+3d, sliding 16-float register window over smem tile.
__global__ void __launch_bounds__(BLOCK_T) main_kernel(
    const float* __restrict__ x, float* __restrict__ out,
    int n_in, int n_out)
{
    __shared__ float xs[TILE_X];
    __shared__ float os[OS_SIZE];
    __shared__ float2 cs[3][28];

    int tid = threadIdx.x;
    int jbase = blockIdx.x * OUT_PER_BLOCK;
    int Mb = (jbase / 3) * 2;
    int g0 = Mb - 45;  // global x index of xs[0]

    if (tid < 84) cs[tid / 28][tid % 28] = g_cpairs[tid];

    #pragma unroll 2
    for (int q = tid; q < TILE_X; q += BLOCK_T) {
        int idx = g0 + q;
        xs[q] = (idx >= 0 && idx < n_in) ? x[idx] : 0.0f;
    }
    __syncthreads();

    int g = tid >> 7;        // phase group, p = 2 - g
    int l = tid & 127;
    int L0 = g + (l << 4);   // local window base: M0 - 55 - g0 = g + 16*l

    float w[16];
    #pragma unroll
    for (int q = 0; q < 16; q++) w[q] = xs[L0 + q];

    float acc[R_OUT];
    #pragma unroll
    for (int d = 0; d < R_OUT; d++) acc[d] = 0.0f;

    const float2* cp = cs[2 - g];

    #pragma unroll
    for (int s = 0; s < 28; s++) {
        float2 c = cp[s];
        #pragma unroll
        for (int d = 0; d < R_OUT; d++) {
            acc[d] = fmaf(w[2 * d], c.x, fmaf(w[2 * d + 1], c.y, acc[d]));
        }
        if (s < 27) {
            #pragma unroll
            for (int q = 0; q < 14; q++) w[q] = w[q + 2];
            w[14] = xs[L0 + 16 + 2 * s];
            w[15] = xs[L0 + 17 + 2 * s];
        }
    }

    // Stage outputs in smem (bank-pad: o + o/32) for coalesced global writes.
    int obase = g + 24 * l;
    #pragma unroll
    for (int d = 0; d < R_OUT; d++) {
        int o = obase + 3 * d;
        os[o + (o >> 5)] = acc[d];
    }
    __syncthreads();

    #pragma unroll
    for (int q = tid; q < OUT_PER_BLOCK; q += BLOCK_T) {
        int j = jbase + q;
        if (j < n_out) out[j] = os[q + (q >> 5)];
    }
}

// Exact two-stage computation for head (j<50, where u-padding matters) and
// tail (j>=n_out, where tail zeros matter). 146 outputs total.
__global__ void edge_kernel(
    const float* __restrict__ x, const float* __restrict__ h,
    const float* __restrict__ b, float* __restrict__ out,
    int n_in, long long n_out, long long out_total)
{
    int t = threadIdx.x;
    long long n_tail = out_total - n_out;
    long long j;
    if (t < 50) j = t;
    else if (t < 50 + n_tail) j = n_out + (t - 50);
    else return;

    float acc = 0.0f;
    for (int s = 0; s < 51; s++) {
        long long k = j - s;
        if (k < 0 || k >= n_out) continue;
        long long mlo = (2 * k - 30 + 2) / 3;  // ceil for the >=0 case; clamped anyway
        if (mlo < 0) mlo = 0;
        long long mhi = (2 * k + 32) / 3;
        if (mhi > (long long)n_in - 1) mhi = (long long)n_in - 1;
        float u = 0.0f;
        for (long long m = mlo; m <= mhi; m++) {
            long long hi = 2 * k + 32 - 3 * m;
            if (hi >= 0 && hi < 63) u = fmaf(x[m], h[hi], u);
        }
        acc = fmaf(b[s], u, acc);
    }
    out[j] = acc;
}

extern "C" void kernel_launch(void* const* d_in, const int* in_sizes, int n_in_arrs,
                              void* d_out, int out_size) {
    const float* x = (const float*)d_in[0];
    const float* h = (const float*)d_in[1];
    const float* b = (const float*)d_in[2];
    float* out = (float*)d_out;

    int n_in = in_sizes[0];  // 8 * 1048576 = 8388608
    long long n3 = (long long)n_in * 3;
    long long n_out = n3 / 2 + ((n3 % 2) ? 1 : 0);  // 12582912
    long long out_total = out_size;                  // 12583008

    prep_kernel<<<1, 192>>>(h, b);

    int grid = (int)((n_out + OUT_PER_BLOCK - 1) / OUT_PER_BLOCK);  // 4096
    main_kernel<<<grid, BLOCK_T>>>(x, out, n_in, (int)n_out);

    edge_kernel<<<1, 256>>>(x, h, b, out, n_in, n_out, out_total);
}

// round 2
// speedup vs baseline: 2.5674x; 2.5674x over previous
#include <cuda_runtime.h>

// Problem constants (UP=3, DOWN=2, Lh=63, Lb=51)
#define R_OUT 8                    // same-phase outputs per thread
#define BLOCK_T 384                // 3 phase groups x 128 threads
#define OUT_PER_BLOCK 3072         // 3 * 128 * R_OUT
#define TILE_X 2104                // 256*R_OUT + 56 (logical floats)
#define XS_PHYS 2240               // TILE_X + TILE_X/16 + pad
#define OS_PHYS 3200               // 3072 + 3072/24

// xs swizzle: pad one float per 16 -> lane stride 16 becomes phys stride 17 (odd, conflict-free)
#define XP(i) ((i) + ((i) >> 4))

// Combined filter C[r] = sum_s b[s]*h[r-2s], r in [0,163). Stored as per-phase
// reversed tap-pairs: cpairs[p*28+s] = (Cp[55-2s], Cp[54-2s]) with Cp[i]=C[p+3i] (0-padded).
__device__ float2 g_cpairs[84];

__global__ void prep_kernel(const float* __restrict__ h, const float* __restrict__ b) {
    __shared__ float C[163];
    int tid = threadIdx.x;
    if (tid < 163) {
        float acc = 0.0f;
        #pragma unroll
        for (int s = 0; s < 51; s++) {
            int idx = tid - 2 * s;
            if (idx >= 0 && idx < 63) acc = fmaf(b[s], h[idx], acc);
        }
        C[tid] = acc;
    }
    __syncthreads();
    if (tid < 84) {
        int p = tid / 28, s = tid % 28;
        int rh = p + 165 - 6 * s;  // C index for tap i_hi = 55-2s
        int rl = p + 162 - 6 * s;  // C index for tap i_lo = 54-2s
        float2 v;
        v.x = (rh <= 162) ? C[rh] : 0.0f;
        v.y = (rl <= 162) ? C[rl] : 0.0f;
        g_cpairs[tid] = v;
    }
}

// Main fused kernel: out[j] = sum_m x[m]*C[2j+32-3m] for j in [0, n_out).
// Phase p = (2j+2)%3; M(j) = (2j+32-p)/3; out[j] = sum_i x[M-i]*C[p+3i].
// Thread layout: group g = tid/128 handles j == g (mod 3), p = 2-g.
// Each thread: R_OUT outputs j0+3d, circular 16-float register window over
// a bank-swizzled smem tile (all indices compile-time -> no register MOVs).
__global__ void __launch_bounds__(BLOCK_T) main_kernel(
    const float* __restrict__ x, float* __restrict__ out,
    int n_in, int n_out)
{
    __shared__ float xs[XS_PHYS];
    __shared__ float os[OS_PHYS];
    __shared__ float2 cs[3][28];

    int tid = threadIdx.x;
    int jbase = blockIdx.x * OUT_PER_BLOCK;
    int Mb = (jbase / 3) * 2;
    int g0 = Mb - 45;  // global x index of logical xs[0]

    if (tid < 84) cs[tid / 28][tid % 28] = g_cpairs[tid];

    #pragma unroll 2
    for (int q = tid; q < TILE_X; q += BLOCK_T) {
        int idx = g0 + q;
        xs[XP(q)] = (idx >= 0 && idx < n_in) ? x[idx] : 0.0f;
    }
    __syncthreads();

    int g = tid >> 7;        // phase group, p = 2 - g
    int l = tid & 127;
    int L0 = g + (l << 4);   // logical local window base

    // Circular window invariant at start of step s: w[(2s+k)&15] = xs_log[L0+2s+k]
    float w[16];
    #pragma unroll
    for (int k = 0; k < 16; k++) w[k] = xs[XP(L0 + k)];

    float acc[R_OUT];
    #pragma unroll
    for (int d = 0; d < R_OUT; d++) acc[d] = 0.0f;

    const float2* cp = cs[2 - g];

    #pragma unroll
    for (int s = 0; s < 28; s++) {
        float2 c = cp[s];
        #pragma unroll
        for (int d = 0; d < R_OUT; d++) {
            acc[d] = fmaf(w[(2 * s + 2 * d) & 15], c.x,
                     fmaf(w[(2 * s + 2 * d + 1) & 15], c.y, acc[d]));
        }
        if (s < 27) {
            w[(2 * s) & 15]     = xs[XP(L0 + 16 + 2 * s)];
            w[(2 * s + 1) & 15] = xs[XP(L0 + 17 + 2 * s)];
        }
    }

    // Stage outputs in smem for coalesced global writes.
    // Logical o = g + 24*l + 3*d ; phys = o + o/24 = 25*l + g + 3*d (stride 25: conflict-free)
    #pragma unroll
    for (int d = 0; d < R_OUT; d++) {
        os[25 * l + g + 3 * d] = acc[d];
    }
    __syncthreads();

    #pragma unroll
    for (int q = tid; q < OUT_PER_BLOCK; q += BLOCK_T) {
        int j = jbase + q;
        if (j < n_out) out[j] = os[q + q / 24];
    }
}

// Exact two-stage computation for head (j<50, where u-padding matters) and
// tail (j>=n_out, where tail zeros matter). 146 outputs total.
__global__ void edge_kernel(
    const float* __restrict__ x, const float* __restrict__ h,
    const float* __restrict__ b, float* __restrict__ out,
    int n_in, long long n_out, long long out_total)
{
    int t = threadIdx.x;
    long long n_tail = out_total - n_out;
    long long j;
    if (t < 50) j = t;
    else if (t < 50 + n_tail) j = n_out + (t - 50);
    else return;

    float acc = 0.0f;
    for (int s = 0; s < 51; s++) {
        long long k = j - s;
        if (k < 0 || k >= n_out) continue;
        long long mlo = (2 * k - 30 + 2) / 3;
        if (mlo < 0) mlo = 0;
        long long mhi = (2 * k + 32) / 3;
        if (mhi > (long long)n_in - 1) mhi = (long long)n_in - 1;
        float u = 0.0f;
        for (long long m = mlo; m <= mhi; m++) {
            long long hi = 2 * k + 32 - 3 * m;
            if (hi >= 0 && hi < 63) u = fmaf(x[m], h[hi], u);
        }
        acc = fmaf(b[s], u, acc);
    }
    out[j] = acc;
}

extern "C" void kernel_launch(void* const* d_in, const int* in_sizes, int n_in_arrs,
                              void* d_out, int out_size) {
    const float* x = (const float*)d_in[0];
    const float* h = (const float*)d_in[1];
    const float* b = (const float*)d_in[2];
    float* out = (float*)d_out;

    int n_in = in_sizes[0];  // 8 * 1048576 = 8388608
    long long n3 = (long long)n_in * 3;
    long long n_out = n3 / 2 + ((n3 % 2) ? 1 : 0);  // 12582912
    long long out_total = out_size;                  // 12583008

    prep_kernel<<<1, 192>>>(h, b);

    int grid = (int)((n_out + OUT_PER_BLOCK - 1) / OUT_PER_BLOCK);  // 4096
    main_kernel<<<grid, BLOCK_T>>>(x, out, n_in, (int)n_out);

    edge_kernel<<<1, 256>>>(x, h, b, out, n_in, n_out, out_total);
}

// round 3
// speedup vs baseline: 2.8085x; 1.0939x over previous
#include <cuda_runtime.h>

// Problem constants (UP=3, DOWN=2, Lh=63, Lb=51)
#define R_OUT 8                    // same-phase outputs per thread
#define BLOCK_T 384                // 3 phase groups x 128 threads
#define OUT_PER_BLOCK 3072         // 3 * 128 * R_OUT
#define TILE_X 2106                // logical floats needed per block
#define XS_PHYS 2368               // TILE_X + 2*(TILE_X/16) rounded up
#define OS_PHYS 3200               // 3072 + 3072/24
#define NSTEP 29                   // packed coefficient steps per phase

// xs swizzle: pad TWO floats per 16 -> lane stride 16 becomes phys stride 18
// (72B; 9l mod 16 covers all residues -> LDS.64 conflict-free) and even
// logical indices stay 8B-aligned (pad is even).
#define XP(i) ((i) + (((i) >> 4) << 1))

// Packed per-phase coefficient pairs: for group g (phase p=2-g, shift e=g&1):
// D_g[t] = (K'[2t], K'[2t+1]) where K'[v] = K[v-e], K[u] = C[p + 3*(55-u)]
// (0 when out of range), C[r] = sum_s b[s]*h[r-2s].
__device__ unsigned long long g_cpk[3 * NSTEP];

__global__ void prep_kernel(const float* __restrict__ h, const float* __restrict__ b) {
    __shared__ float C[163];
    int tid = threadIdx.x;
    if (tid < 163) {
        float acc = 0.0f;
        #pragma unroll
        for (int s = 0; s < 51; s++) {
            int idx = tid - 2 * s;
            if (idx >= 0 && idx < 63) acc = fmaf(b[s], h[idx], acc);
        }
        C[tid] = acc;
    }
    __syncthreads();
    if (tid < 3 * NSTEP) {
        int g = tid / NSTEP, t = tid % NSTEP;
        int p = 2 - g, e = g & 1;
        float half_v[2];
        #pragma unroll
        for (int q = 0; q < 2; q++) {
            int v = 2 * t + q;
            int u = v - e;
            float val = 0.0f;
            if (u >= 0 && u <= 55) {
                int idx = p + 3 * (55 - u);
                if (idx <= 162) val = C[idx];
            }
            half_v[q] = val;
        }
        unsigned long long pk =
            (unsigned long long)__float_as_uint(half_v[0]) |
            ((unsigned long long)__float_as_uint(half_v[1]) << 32);
        g_cpk[tid] = pk;
    }
}

__device__ __forceinline__ unsigned long long fma_f32x2(
    unsigned long long a, unsigned long long bb, unsigned long long c) {
    unsigned long long d;
    asm("fma.rn.f32x2 %0, %1, %2, %3;" : "=l"(d) : "l"(a), "l"(bb), "l"(c));
    return d;
}

// Main fused kernel: out[j] = sum_m x[m]*C[2j+32-3m].
// Group g = tid/128 handles j == g (mod 3). Each thread: 8 outputs j0+3d.
// Packed form: acc2[d] (f32x2) accumulates over 29 steps; window = 8 packed
// pairs (circular), refilled with one LDS.64 per step. Final: sum halves.
__global__ void __launch_bounds__(BLOCK_T) main_kernel(
    const float* __restrict__ x, float* __restrict__ out,
    int n_in, int n_out)
{
    __shared__ float xs[XS_PHYS];
    __shared__ float os[OS_PHYS];
    __shared__ unsigned long long cs[3][NSTEP];

    int tid = threadIdx.x;
    int jbase = blockIdx.x * OUT_PER_BLOCK;
    int Mb = (jbase / 3) * 2;
    int g0 = Mb - 45;  // global x index of logical xs[0]

    if (tid < 3 * NSTEP) cs[tid / NSTEP][tid % NSTEP] = g_cpk[tid];

    #pragma unroll 2
    for (int q = tid; q < TILE_X; q += BLOCK_T) {
        int idx = g0 + q;
        xs[XP(q)] = (idx >= 0 && idx < n_in) ? x[idx] : 0.0f;
    }
    __syncthreads();

    int g = tid >> 7;           // phase group
    int l = tid & 127;
    int E0 = (g & 2) + (l << 4);  // even window base (g=1 shifted down by 1)

    // Circular packed window: pair k = {xs[E0+2k], xs[E0+2k+1]}
    unsigned long long w2[8];
    #pragma unroll
    for (int k = 0; k < 8; k++)
        w2[k] = *(const unsigned long long*)&xs[XP(E0 + 2 * k)];

    unsigned long long acc2[R_OUT];
    #pragma unroll
    for (int d = 0; d < R_OUT; d++) acc2[d] = 0ull;

    const unsigned long long* cp = cs[g];

    #pragma unroll
    for (int t = 0; t < NSTEP; t++) {
        unsigned long long c = cp[t];
        #pragma unroll
        for (int d = 0; d < R_OUT; d++)
            acc2[d] = fma_f32x2(w2[(t + d) & 7], c, acc2[d]);
        if (t < NSTEP - 1)
            w2[t & 7] = *(const unsigned long long*)&xs[XP(E0 + 2 * (t + 8))];
    }

    // Stage outputs in smem for coalesced global writes.
    // Logical o = g + 24*l + 3*d ; phys = 25*l + g + 3*d (stride 25: conflict-free)
    #pragma unroll
    for (int d = 0; d < R_OUT; d++) {
        float lo = __uint_as_float((unsigned)(acc2[d] & 0xffffffffull));
        float hi = __uint_as_float((unsigned)(acc2[d] >> 32));
        os[25 * l + g + 3 * d] = lo + hi;
    }
    __syncthreads();

    #pragma unroll
    for (int q = tid; q < OUT_PER_BLOCK; q += BLOCK_T) {
        int j = jbase + q;
        if (j < n_out) out[j] = os[q + q / 24];
    }
}

// Exact two-stage computation for head (j<50, u-padding) and tail (j>=n_out).
__global__ void edge_kernel(
    const float* __restrict__ x, const float* __restrict__ h,
    const float* __restrict__ b, float* __restrict__ out,
    int n_in, long long n_out, long long out_total)
{
    int t = threadIdx.x;
    long long n_tail = out_total - n_out;
    long long j;
    if (t < 50) j = t;
    else if (t < 50 + n_tail) j = n_out + (t - 50);
    else return;

    float acc = 0.0f;
    for (int s = 0; s < 51; s++) {
        long long k = j - s;
        if (k < 0 || k >= n_out) continue;
        long long mlo = (2 * k - 30 + 2) / 3;
        if (mlo < 0) mlo = 0;
        long long mhi = (2 * k + 32) / 3;
        if (mhi > (long long)n_in - 1) mhi = (long long)n_in - 1;
        float u = 0.0f;
        for (long long m = mlo; m <= mhi; m++) {
            long long hi = 2 * k + 32 - 3 * m;
            if (hi >= 0 && hi < 63) u = fmaf(x[m], h[hi], u);
        }
        acc = fmaf(b[s], u, acc);
    }
    out[j] = acc;
}

extern "C" void kernel_launch(void* const* d_in, const int* in_sizes, int n_in_arrs,
                              void* d_out, int out_size) {
    const float* x = (const float*)d_in[0];
    const float* h = (const float*)d_in[1];
    const float* b = (const float*)d_in[2];
    float* out = (float*)d_out;

    int n_in = in_sizes[0];  // 8 * 1048576 = 8388608
    long long n3 = (long long)n_in * 3;
    long long n_out = n3 / 2 + ((n3 % 2) ? 1 : 0);  // 12582912
    long long out_total = out_size;                  // 12583008

    prep_kernel<<<1, 192>>>(h, b);

    int grid = (int)((n_out + OUT_PER_BLOCK - 1) / OUT_PER_BLOCK);  // 4096
    main_kernel<<<grid, BLOCK_T>>>(x, out, n_in, (int)n_out);

    edge_kernel<<<1, 256>>>(x, h, b, out, n_in, n_out, out_total);
}

// round 4
// speedup vs baseline: 3.9164x; 1.3945x over previous
#include <cuda_runtime.h>

// Problem constants (UP=3, DOWN=2, Lh=63, Lb=51)
#define R_OUT 8                    // same-phase outputs per thread
#define BLOCK_T 384                // 3 phase groups x 128 threads
#define OUT_PER_BLOCK 3072         // 3 * 128 * R_OUT
#define TILE_X 2106                // logical floats needed per block
#define XS_PHYS 2368               // swizzled tile size
#define OS_PHYS 3200               // 3072 + 3072/24
#define NSTEP 29                   // packed coefficient steps per phase

// xs swizzle: pad TWO floats per 16 -> lane stride 16 becomes phys stride 18
// (72B; conflict-free LDS.64) and even logical indices stay 8B-aligned.
#define XP(i) ((i) + (((i) >> 4) << 1))

__device__ __forceinline__ unsigned long long fma_f32x2(
    unsigned long long a, unsigned long long bb, unsigned long long c) {
    unsigned long long d;
    asm("fma.rn.f32x2 %0, %1, %2, %3;" : "=l"(d) : "l"(a), "l"(bb), "l"(c));
    return d;
}

// Exact two-stage value for edge outputs (head j<50 where u-padding matters,
// tail j>=n_out where appended zeros matter).
__device__ float edge_value(const float* __restrict__ x,
                            const float* __restrict__ h,
                            const float* __restrict__ b,
                            long long j, int n_in, long long n_out) {
    float acc = 0.0f;
    for (int s = 0; s < 51; s++) {
        long long k = j - s;
        if (k < 0 || k >= n_out) continue;
        long long mlo = (2 * k - 30 + 2) / 3;
        if (mlo < 0) mlo = 0;
        long long mhi = (2 * k + 32) / 3;
        if (mhi > (long long)n_in - 1) mhi = (long long)n_in - 1;
        float u = 0.0f;
        for (long long m = mlo; m <= mhi; m++) {
            long long hi = 2 * k + 32 - 3 * m;
            if (hi >= 0 && hi < 63) u = fmaf(x[m], h[hi], u);
        }
        acc = fmaf(b[s], u, acc);
    }
    return acc;
}

// Fused single kernel.
// out[j] = sum_m x[m]*C[2j+32-3m], C[r] = sum_s b[s]*h[r-2s] (r in [0,163)).
// Group g = tid/128 handles j == g (mod 3); each thread: 8 outputs j0+3d via
// f32x2 packed FMAs over a circular 8-pair register window on a swizzled tile.
__global__ void __launch_bounds__(BLOCK_T) fused_kernel(
    const float* __restrict__ x, const float* __restrict__ h,
    const float* __restrict__ b, float* __restrict__ out,
    int n_in, int n_out, int out_total)
{
    __shared__ float xs[XS_PHYS];
    __shared__ float os[OS_PHYS];
    __shared__ float C[164];
    __shared__ unsigned long long cs[3][NSTEP];

    int tid = threadIdx.x;
    int bx = blockIdx.x;
    int jbase = bx * OUT_PER_BLOCK;
    int g0 = (jbase / 3) * 2 - 45;  // global x index of logical xs[0]

    // --- per-block coefficient computation (replaces prep kernel) ---
    if (tid < 163) {
        float acc = 0.0f;
        #pragma unroll
        for (int s = 0; s < 51; s++) {
            int idx = tid - 2 * s;
            if (idx >= 0 && idx < 63) acc = fmaf(b[s], h[idx], acc);
        }
        C[tid] = acc;
    }

    // --- input tile load (interior blocks: no bounds checks) ---
    if (bx != 0 && bx != (int)gridDim.x - 1) {
        #pragma unroll
        for (int q = tid; q < TILE_X; q += BLOCK_T)
            xs[XP(q)] = __ldg(&x[g0 + q]);
    } else {
        #pragma unroll
        for (int q = tid; q < TILE_X; q += BLOCK_T) {
            int idx = g0 + q;
            xs[XP(q)] = (idx >= 0 && idx < n_in) ? x[idx] : 0.0f;
        }
    }
    __syncthreads();

    // --- pack per-phase coefficient pairs ---
    // cs[g][t] = (K'[2t], K'[2t+1]), K'[v] = K[v - (g&1)], K[u] = C[(2-g) + 3*(55-u)]
    if (tid < 3 * NSTEP) {
        int g = tid / NSTEP, t = tid % NSTEP;
        int p = 2 - g, e = g & 1;
        float hv[2];
        #pragma unroll
        for (int q = 0; q < 2; q++) {
            int u = 2 * t + q - e;
            float val = 0.0f;
            if (u >= 0 && u <= 55) {
                int idx = p + 3 * (55 - u);
                if (idx <= 162) val = C[idx];
            }
            hv[q] = val;
        }
        cs[g][t] = (unsigned long long)__float_as_uint(hv[0]) |
                   ((unsigned long long)__float_as_uint(hv[1]) << 32);
    }
    __syncthreads();

    // --- main packed FIR loop ---
    int g = tid >> 7;
    int l = tid & 127;
    int E0 = (g & 2) + (l << 4);  // even window base (g=1 shifted down 1, folded into coeffs)

    unsigned long long w2[8];
    #pragma unroll
    for (int k = 0; k < 8; k++)
        w2[k] = *(const unsigned long long*)&xs[XP(E0 + 2 * k)];

    unsigned long long acc2[R_OUT];
    #pragma unroll
    for (int d = 0; d < R_OUT; d++) acc2[d] = 0ull;

    const unsigned long long* cp = cs[g];

    #pragma unroll
    for (int t = 0; t < NSTEP; t++) {
        unsigned long long c = cp[t];
        #pragma unroll
        for (int d = 0; d < R_OUT; d++)
            acc2[d] = fma_f32x2(w2[(t + d) & 7], c, acc2[d]);
        if (t < NSTEP - 1)
            w2[t & 7] = *(const unsigned long long*)&xs[XP(E0 + 2 * (t + 8))];
    }

    // --- stage outputs: logical o = g + 24*l + 3*d, phys 25*l + g + 3*d ---
    #pragma unroll
    for (int d = 0; d < R_OUT; d++) {
        float lo = __uint_as_float((unsigned)(acc2[d] & 0xffffffffull));
        float hi = __uint_as_float((unsigned)(acc2[d] >> 32));
        os[25 * l + g + 3 * d] = lo + hi;
    }
    __syncthreads();

    // --- coalesced vectorized writeback ---
    if (jbase >= 50 && jbase + OUT_PER_BLOCK <= n_out) {
        #pragma unroll
        for (int it = 0; it < OUT_PER_BLOCK / (4 * BLOCK_T); it++) {
            int q4 = 4 * tid + it * 4 * BLOCK_T;
            float4 v;
            v.x = os[q4 + q4 / 24];
            v.y = os[(q4 + 1) + (q4 + 1) / 24];
            v.z = os[(q4 + 2) + (q4 + 2) / 24];
            v.w = os[(q4 + 3) + (q4 + 3) / 24];
            *(float4*)&out[jbase + q4] = v;
        }
    } else {
        #pragma unroll
        for (int q = tid; q < OUT_PER_BLOCK; q += BLOCK_T) {
            int j = jbase + q;
            // j >= 50 (head handled exactly below) and j < n_out
            if ((unsigned)(j - 50) < (unsigned)(n_out - 50)) out[j] = os[q + q / 24];
        }
    }

    // --- block 0: exact edge outputs (head + tail), replaces edge kernel ---
    if (bx == 0) {
        int n_tail = out_total - n_out;
        if (tid < 50 + n_tail) {
            long long j = (tid < 50) ? (long long)tid
                                     : (long long)n_out + (tid - 50);
            out[j] = edge_value(x, h, b, j, n_in, (long long)n_out);
        }
    }
}

extern "C" void kernel_launch(void* const* d_in, const int* in_sizes, int n_in_arrs,
                              void* d_out, int out_size) {
    const float* x = (const float*)d_in[0];
    const float* h = (const float*)d_in[1];
    const float* b = (const float*)d_in[2];
    float* out = (float*)d_out;

    int n_in = in_sizes[0];  // 8 * 1048576 = 8388608
    long long n3 = (long long)n_in * 3;
    long long n_out = n3 / 2 + ((n3 % 2) ? 1 : 0);  // 12582912
    int out_total = out_size;                        // 12583008

    int grid = (int)((n_out + OUT_PER_BLOCK - 1) / OUT_PER_BLOCK);  // 4096
    fused_kernel<<<grid, BLOCK_T>>>(x, h, b, out, n_in, (int)n_out, out_total);
}